// round 10
// baseline (speedup 1.0000x reference)
#include <cuda_runtime.h>
#include <cuda_bf16.h>
#include <cstdint>
#include <math.h>

// Problem constants
#define NROWS 2048
#define VDIM  50257
#define VPAD  50272   // bf16 row stride
#define H_S   2048
#define H_T   4096

// Scratch (static device allocations)
__device__ __nv_bfloat16 g_logits_s[(size_t)NROWS * VPAD];  // 206 MB
__device__ __nv_bfloat16 g_logits_t[(size_t)NROWS * VPAD];  // 206 MB
__device__ __nv_bfloat16 g_as_bf[(size_t)NROWS * H_S];
__device__ __nv_bfloat16 g_at_bf[(size_t)NROWS * H_T];
__device__ float g_row_ce[NROWS];
__device__ float g_row_valid[NROWS];
__device__ float g_row_kls[NROWS];
__device__ float g_row_klt[NROWS];

// ---------------------------------------------------------------------------
// Helpers
// ---------------------------------------------------------------------------
__device__ __forceinline__ uint32_t swz(uint32_t row, uint32_t chunk) {
    // 128-byte logical rows (64 bf16), 16B chunks, XOR swizzle
    return row * 128u + ((chunk ^ (row & 7u)) << 4);
}
__device__ __forceinline__ void cp16(uint32_t saddr, const void* gaddr) {
    asm volatile("cp.async.cg.shared.global [%0], [%1], 16;\n"
                 :: "r"(saddr), "l"(gaddr) : "memory");
}
__device__ __forceinline__ uint32_t pack_bf16x2(float a, float b) {
    __nv_bfloat162 p = __floats2bfloat162_rn(a, b);
    return *(uint32_t*)&p;
}

// ---------------------------------------------------------------------------
// fp32 -> bf16 for activations (lossless; small tensors)
// ---------------------------------------------------------------------------
__global__ __launch_bounds__(256) void cvt_kernel(
    const float* __restrict__ src, __nv_bfloat16* __restrict__ dst, size_t n4)
{
    for (size_t i = (size_t)blockIdx.x * 256 + threadIdx.x; i < n4;
         i += (size_t)gridDim.x * 256) {
        float4 v = *(const float4*)(src + i * 4);
        *(uint2*)(dst + i * 4) =
            make_uint2(pack_bf16x2(v.x, v.y), pack_bf16x2(v.z, v.w));
    }
}

// ---------------------------------------------------------------------------
// GEMM: C[n,v] = sum_h A[n,h] * B[v,h]
//   A: bf16 [NROWS,H] (pre-converted acts) via cp.async
//   B: FP32 [VDIM,H] weights, loaded LDG.128 register-staged, converted to
//      bf16 in-flight, STS.128 into the validated swizzled layout
// CTA tile 128x128x64, 8 warps (2x4), warp tile 64x32, k16 mma + ldmatrix.
// Double-buffered (2 stages x 32KB = 64KB smem).
// ---------------------------------------------------------------------------
__global__ __launch_bounds__(256) void gemm_fusedcvt_kernel(
    const __nv_bfloat16* __restrict__ A,   // [NROWS, H] bf16
    const float* __restrict__ B,           // [VDIM, H]  fp32
    __nv_bfloat16* __restrict__ C,         // [NROWS, VPAD] bf16
    int H)
{
    extern __shared__ char smem[];
    const uint32_t sA = (uint32_t)__cvta_generic_to_shared(smem);
    const uint32_t sB = sA + 32768;   // A: 2 x 16KB, then B: 2 x 16KB

    const int tid   = threadIdx.x;
    const int lane  = tid & 31;
    const int warp  = tid >> 5;
    const int warp_m = warp >> 2;   // 0..1
    const int warp_n = warp & 3;    // 0..3
    const int m0 = blockIdx.x * 128;
    const int v0 = blockIdx.y * 128;

    float acc[4][4][4];
    #pragma unroll
    for (int i = 0; i < 4; i++)
        #pragma unroll
        for (int j = 0; j < 4; j++)
            #pragma unroll
            for (int k = 0; k < 4; k++) acc[i][j][k] = 0.f;

    const int ktiles = H >> 6;
    const int lr = tid >> 3;    // 0..31 (row group)
    const int lc = tid & 7;     // 16B-bf16 chunk 0..7 (= 8 k-elems)

    size_t aoff[4], boff[4];
    #pragma unroll
    for (int j = 0; j < 4; j++) {
        aoff[j] = (size_t)(m0 + lr + j * 32) * H;
        int vr = v0 + lr + j * 32;
        if (vr > VDIM - 1) vr = VDIM - 1;   // clamp; clamped rows never stored
        boff[j] = (size_t)vr * H;
    }

    float4 rb[4][2];   // staged fp32 B: 4 row-groups x 8 floats

    auto ldg_b = [&](int kt) {
        const int k0 = kt * 64;
        #pragma unroll
        for (int j = 0; j < 4; j++) {
            const float* p = B + boff[j] + k0 + lc * 8;
            rb[j][0] = *(const float4*)(p);
            rb[j][1] = *(const float4*)(p + 4);
        }
    };
    auto cpa_a = [&](int slot, int kt) {
        const int k0 = kt * 64;
        #pragma unroll
        for (int j = 0; j < 4; j++)
            cp16(sA + slot * 16384 + swz(lr + j * 32, lc), A + aoff[j] + k0 + lc * 8);
        asm volatile("cp.async.commit_group;\n" ::: "memory");
    };
    auto sts_b = [&](int slot) {
        #pragma unroll
        for (int j = 0; j < 4; j++) {
            uint4 o = make_uint4(
                pack_bf16x2(rb[j][0].x, rb[j][0].y),
                pack_bf16x2(rb[j][0].z, rb[j][0].w),
                pack_bf16x2(rb[j][1].x, rb[j][1].y),
                pack_bf16x2(rb[j][1].z, rb[j][1].w));
            uint32_t addr = sB + slot * 16384 + swz(lr + j * 32, lc);
            asm volatile("st.shared.v4.b32 [%0], {%1,%2,%3,%4};\n"
                :: "r"(addr), "r"(o.x), "r"(o.y), "r"(o.z), "r"(o.w));
        }
    };

    // Prologue: stage 0
    ldg_b(0);
    cpa_a(0, 0);
    sts_b(0);
    asm volatile("cp.async.wait_group 0;\n" ::: "memory");
    __syncthreads();

    for (int kt = 0; kt < ktiles; kt++) {
        const int slot = kt & 1;
        if (kt + 1 < ktiles) {
            ldg_b(kt + 1);           // issue early: DRAM latency hides under mma
            cpa_a(slot ^ 1, kt + 1); // slot^1 fully consumed in iter kt-1 (synced)
        }

        const uint32_t aBase = sA + slot * 16384;
        const uint32_t bBase = sB + slot * 16384;
        #pragma unroll
        for (int kk = 0; kk < 4; kk++) {
            uint32_t a[4][4], b[4][2];
            #pragma unroll
            for (int mf = 0; mf < 4; mf++) {
                uint32_t row = warp_m * 64 + mf * 16 + (lane & 15);
                uint32_t chunk = kk * 2 + (lane >> 4);
                asm volatile("ldmatrix.sync.aligned.m8n8.x4.shared.b16 {%0,%1,%2,%3}, [%4];\n"
                    : "=r"(a[mf][0]), "=r"(a[mf][1]), "=r"(a[mf][2]), "=r"(a[mf][3])
                    : "r"(aBase + swz(row, chunk)));
            }
            #pragma unroll
            for (int nf = 0; nf < 4; nf++) {
                uint32_t row = warp_n * 32 + nf * 8 + (lane & 7);
                uint32_t chunk = kk * 2 + ((lane >> 3) & 1);
                asm volatile("ldmatrix.sync.aligned.m8n8.x2.shared.b16 {%0,%1}, [%2];\n"
                    : "=r"(b[nf][0]), "=r"(b[nf][1]) : "r"(bBase + swz(row, chunk)));
            }
            #pragma unroll
            for (int mf = 0; mf < 4; mf++)
                #pragma unroll
                for (int nf = 0; nf < 4; nf++)
                    asm volatile(
                        "mma.sync.aligned.m16n8k16.row.col.f32.bf16.bf16.f32 "
                        "{%0,%1,%2,%3}, {%4,%5,%6,%7}, {%8,%9}, {%0,%1,%2,%3};\n"
                        : "+f"(acc[mf][nf][0]), "+f"(acc[mf][nf][1]),
                          "+f"(acc[mf][nf][2]), "+f"(acc[mf][nf][3])
                        : "r"(a[mf][0]), "r"(a[mf][1]), "r"(a[mf][2]), "r"(a[mf][3]),
                          "r"(b[nf][0]), "r"(b[nf][1]));
        }

        if (kt + 1 < ktiles) {
            sts_b(slot ^ 1);         // write side of next stage
            asm volatile("cp.async.wait_group 0;\n" ::: "memory");
        }
        __syncthreads();             // next stage ready; this stage reusable
    }

    // Epilogue: bf16 stores (reference bf16 quantization grid)
    const int row_in = lane >> 2;
    const int col_in = (lane & 3) * 2;
    #pragma unroll
    for (int mf = 0; mf < 4; mf++) {
        #pragma unroll
        for (int nf = 0; nf < 4; nf++) {
            int n0 = m0 + warp_m * 64 + mf * 16 + row_in;
            int v  = v0 + warp_n * 32 + nf * 8 + col_in;
            __nv_bfloat16* r0 = C + (size_t)n0 * VPAD;
            __nv_bfloat16* r1 = C + (size_t)(n0 + 8) * VPAD;
            if (v + 1 < VDIM) {
                *(__nv_bfloat162*)(r0 + v) = __floats2bfloat162_rn(acc[mf][nf][0], acc[mf][nf][1]);
                *(__nv_bfloat162*)(r1 + v) = __floats2bfloat162_rn(acc[mf][nf][2], acc[mf][nf][3]);
            } else if (v < VDIM) {
                r0[v] = __float2bfloat16_rn(acc[mf][nf][0]);
                r1[v] = __float2bfloat16_rn(acc[mf][nf][2]);
            }
        }
    }
}

// ---------------------------------------------------------------------------
// Fused per-row loss: pass 1 = online lse (both rows); pass 2 (L2-hot) = JSD.
// ---------------------------------------------------------------------------
#define NPAIR (VDIM / 2)   // 25128; tail element VDIM-1 by thread 0
__global__ __launch_bounds__(256) void rowloss_kernel(const int* __restrict__ target) {
    const int n = blockIdx.x;
    const __nv_bfloat16* rs = g_logits_s + (size_t)n * VPAD;
    const __nv_bfloat16* rt = g_logits_t + (size_t)n * VPAD;
    const __nv_bfloat162* rs2 = (const __nv_bfloat162*)rs;
    const __nv_bfloat162* rt2 = (const __nv_bfloat162*)rt;

    __shared__ float sh0[256], sh1[256], sh2[256], sh3[256];
    __shared__ float s_ls, s_lt;

    float ms = -INFINITY, ss = 0.f, mt = -INFINITY, st = 0.f;
    for (int p = threadIdx.x; p < NPAIR; p += 256) {
        __nv_bfloat162 xs2 = rs2[p], xt2 = rt2[p];
        float s0 = __bfloat162float(xs2.x), s1 = __bfloat162float(xs2.y);
        float t0 = __bfloat162float(xt2.x), t1 = __bfloat162float(xt2.y);
        float nms = fmaxf(ms, fmaxf(s0, s1));
        ss = ss * __expf(ms - nms) + __expf(s0 - nms) + __expf(s1 - nms);
        ms = nms;
        float nmt = fmaxf(mt, fmaxf(t0, t1));
        st = st * __expf(mt - nmt) + __expf(t0 - nmt) + __expf(t1 - nmt);
        mt = nmt;
    }
    if (threadIdx.x == 0) {
        float s0 = __bfloat162float(rs[VDIM - 1]);
        float nms = fmaxf(ms, s0);
        ss = ss * __expf(ms - nms) + __expf(s0 - nms); ms = nms;
        float t0 = __bfloat162float(rt[VDIM - 1]);
        float nmt = fmaxf(mt, t0);
        st = st * __expf(mt - nmt) + __expf(t0 - nmt); mt = nmt;
    }
    sh0[threadIdx.x] = ms; sh1[threadIdx.x] = ss;
    sh2[threadIdx.x] = mt; sh3[threadIdx.x] = st;
    __syncthreads();
    for (int off = 128; off > 0; off >>= 1) {
        if (threadIdx.x < off) {
            float m2 = sh0[threadIdx.x + off], s2 = sh1[threadIdx.x + off];
            float m1 = sh0[threadIdx.x],       s1 = sh1[threadIdx.x];
            float nm = fmaxf(m1, m2);
            sh1[threadIdx.x] = s1 * __expf(m1 - nm) + s2 * __expf(m2 - nm);
            sh0[threadIdx.x] = nm;
            m2 = sh2[threadIdx.x + off]; s2 = sh3[threadIdx.x + off];
            m1 = sh2[threadIdx.x];       s1 = sh3[threadIdx.x];
            nm = fmaxf(m1, m2);
            sh3[threadIdx.x] = s1 * __expf(m1 - nm) + s2 * __expf(m2 - nm);
            sh2[threadIdx.x] = nm;
        }
        __syncthreads();
    }
    if (threadIdx.x == 0) {
        s_ls = sh0[0] + __logf(sh1[0]);
        s_lt = sh2[0] + __logf(sh3[0]);
    }
    __syncthreads();
    const float ls = s_ls, lt = s_lt;

    float as = 0.f, at = 0.f;
    for (int p = threadIdx.x; p < NPAIR; p += 256) {
        __nv_bfloat162 s2v = rs2[p], t2v = rt2[p];
        #pragma unroll
        for (int h = 0; h < 2; h++) {
            float sv = __bfloat162float(h ? s2v.y : s2v.x);
            float tv = __bfloat162float(h ? t2v.y : t2v.x);
            float slp = sv - ls, tlp = tv - lt;
            float sp = __expf(slp), tp = __expf(tlp);
            float lm = __logf(0.5f * sp + 0.5f * tp);   // BETA = 0.5
            as += sp * (slp - lm);
            at += tp * (tlp - lm);
        }
    }
    if (threadIdx.x == 0) {
        float slp = __bfloat162float(rs[VDIM - 1]) - ls;
        float tlp = __bfloat162float(rt[VDIM - 1]) - lt;
        float sp = __expf(slp), tp = __expf(tlp);
        float lm = __logf(0.5f * sp + 0.5f * tp);
        as += sp * (slp - lm);
        at += tp * (tlp - lm);
    }
    sh0[threadIdx.x] = as; sh1[threadIdx.x] = at;
    __syncthreads();
    for (int off = 128; off > 0; off >>= 1) {
        if (threadIdx.x < off) {
            sh0[threadIdx.x] += sh0[threadIdx.x + off];
            sh1[threadIdx.x] += sh1[threadIdx.x + off];
        }
        __syncthreads();
    }
    if (threadIdx.x == 0) {
        g_row_kls[n] = sh0[0];
        g_row_klt[n] = sh1[0];
        int tg = target[n];
        bool valid = (tg != -100);
        int tgs = valid ? tg : 0;
        g_row_ce[n]    = valid ? (ls - __bfloat162float(rs[tgs])) : 0.f;
        g_row_valid[n] = valid ? 1.f : 0.f;
    }
}

// ---------------------------------------------------------------------------
// Final combine -> scalar loss (deterministic).
// ---------------------------------------------------------------------------
__global__ __launch_bounds__(256) void combine_kernel(float* __restrict__ out) {
    __shared__ float s0[256], s1[256], s2[256], s3[256];
    float a = 0.f, b = 0.f, c = 0.f, d = 0.f;
    for (int n = threadIdx.x; n < NROWS; n += 256) {
        a += g_row_ce[n];
        b += g_row_valid[n];
        c += g_row_kls[n];
        d += g_row_klt[n];
    }
    s0[threadIdx.x] = a; s1[threadIdx.x] = b; s2[threadIdx.x] = c; s3[threadIdx.x] = d;
    __syncthreads();
    for (int off = 128; off > 0; off >>= 1) {
        if (threadIdx.x < off) {
            s0[threadIdx.x] += s0[threadIdx.x + off];
            s1[threadIdx.x] += s1[threadIdx.x + off];
            s2[threadIdx.x] += s2[threadIdx.x + off];
            s3[threadIdx.x] += s3[threadIdx.x + off];
        }
        __syncthreads();
    }
    if (threadIdx.x == 0) {
        float hard = s0[0] / s1[0];
        float jsd  = (0.5f * s3[0] + 0.5f * s2[0]) / (float)NROWS;  // BETA=0.5
        out[0] = 0.5f * hard + 0.5f * jsd;
    }
}

// ---------------------------------------------------------------------------
// Launch.  Inputs are FLOAT32 (harness widens bf16); identified by size.
// ---------------------------------------------------------------------------
extern "C" void kernel_launch(void* const* d_in, const int* in_sizes, int n_in,
                              void* d_out, int out_size) {
    const float* student = nullptr;
    const float* W_s     = nullptr;
    const float* teacher = nullptr;
    const float* W_t     = nullptr;
    const int*   target  = nullptr;

    for (int i = 0; i < n_in; i++) {
        long sz = in_sizes[i];
        if      (sz == (long)NROWS * H_S)      student = (const float*)d_in[i];
        else if (sz == (long)VDIM  * H_S)      W_s     = (const float*)d_in[i];
        else if (sz == (long)NROWS * H_T)      teacher = (const float*)d_in[i];
        else if (sz == (long)VDIM  * H_T)      W_t     = (const float*)d_in[i];
        else if (sz == (long)NROWS)            target  = (const int*)d_in[i];
    }

    __nv_bfloat16 *Cs, *Ct, *asb, *atb;
    cudaGetSymbolAddress((void**)&Cs,  g_logits_s);
    cudaGetSymbolAddress((void**)&Ct,  g_logits_t);
    cudaGetSymbolAddress((void**)&asb, g_as_bf);
    cudaGetSymbolAddress((void**)&atb, g_at_bf);

    cudaFuncSetAttribute(gemm_fusedcvt_kernel,
                         cudaFuncAttributeMaxDynamicSharedMemorySize, 65536);

    // Activation fp32 -> bf16 (small: ~63 MB total traffic)
    cvt_kernel<<<1024, 256>>>(student, asb, (size_t)NROWS * H_S / 4);
    cvt_kernel<<<1024, 256>>>(teacher, atb, (size_t)NROWS * H_T / 4);

    dim3 ggrid(NROWS / 128, (VDIM + 127) / 128);   // (16, 393), M innermost
    gemm_fusedcvt_kernel<<<ggrid, 256, 65536>>>(asb, W_s, Cs, H_S);
    gemm_fusedcvt_kernel<<<ggrid, 256, 65536>>>(atb, W_t, Ct, H_T);

    rowloss_kernel<<<NROWS, 256>>>(target);
    combine_kernel<<<1, 256>>>((float*)d_out);
}

// round 11
// speedup vs baseline: 1.5733x; 1.5733x over previous
#include <cuda_runtime.h>
#include <cuda_bf16.h>
#include <cstdint>
#include <math.h>

// Problem constants
#define NROWS 2048
#define VDIM  50257
#define VPAD  50272   // bf16 row stride
#define H_S   2048
#define H_T   4096

// Scratch (static device allocations)
__device__ __nv_bfloat16 g_logits_s[(size_t)NROWS * VPAD];  // 206 MB
__device__ __nv_bfloat16 g_logits_t[(size_t)NROWS * VPAD];  // 206 MB
__device__ __nv_bfloat16 g_Ws_bf[(size_t)VDIM * H_S];       // 206 MB
__device__ __nv_bfloat16 g_Wt_bf[(size_t)VDIM * H_T];       // 412 MB
__device__ __nv_bfloat16 g_as_bf[(size_t)NROWS * H_S];
__device__ __nv_bfloat16 g_at_bf[(size_t)NROWS * H_T];
__device__ float g_row_ce[NROWS];
__device__ float g_row_valid[NROWS];
__device__ float g_row_kls[NROWS];
__device__ float g_row_klt[NROWS];

// ---------------------------------------------------------------------------
// Helpers
// ---------------------------------------------------------------------------
__device__ __forceinline__ uint32_t swz(uint32_t row, uint32_t chunk) {
    // 128-byte logical rows (64 bf16), 16B chunks, XOR swizzle
    return row * 128u + ((chunk ^ (row & 7u)) << 4);
}
__device__ __forceinline__ void cp16(uint32_t saddr, const void* gaddr) {
    asm volatile("cp.async.cg.shared.global [%0], [%1], 16;\n"
                 :: "r"(saddr), "l"(gaddr) : "memory");
}
__device__ __forceinline__ uint32_t pack_bf16x2(float a, float b) {
    __nv_bfloat162 p = __floats2bfloat162_rn(a, b);
    return *(uint32_t*)&p;
}

// ---------------------------------------------------------------------------
// fp32 -> bf16 (lossless).  8 elems/thread/iter: 2x LDG.128 + 1x STG.128.
// ---------------------------------------------------------------------------
__global__ __launch_bounds__(256) void cvt_kernel(
    const float* __restrict__ src, __nv_bfloat16* __restrict__ dst, size_t n8)
{
    const size_t stride = (size_t)gridDim.x * 256;
    for (size_t i = (size_t)blockIdx.x * 256 + threadIdx.x; i < n8; i += stride) {
        const float4* p = (const float4*)(src + i * 8);
        float4 v0 = p[0], v1 = p[1];
        uint4 o = make_uint4(pack_bf16x2(v0.x, v0.y), pack_bf16x2(v0.z, v0.w),
                             pack_bf16x2(v1.x, v1.y), pack_bf16x2(v1.z, v1.w));
        *(uint4*)(dst + i * 8) = o;
    }
}

// ---------------------------------------------------------------------------
// GEMM (R8 config, verbatim): C[n,v] = sum_h A[n,h]*B[v,h]
// bf16 in, fp32 accum, bf16 out.  CTA 128x128x64, 8 warps (2x4), warp 64x32.
// Double-buffered cp.async (wait_group 1), k16 mma + ldmatrix.
// ---------------------------------------------------------------------------
__global__ __launch_bounds__(256) void gemm_bf16_kernel(
    const __nv_bfloat16* __restrict__ A,   // [NROWS, H]
    const __nv_bfloat16* __restrict__ B,   // [VDIM, H]
    __nv_bfloat16* __restrict__ C,         // [NROWS, VPAD]
    int H)
{
    extern __shared__ char smem[];

    const int tid   = threadIdx.x;
    const int lane  = tid & 31;
    const int warp  = tid >> 5;
    const int warp_m = warp >> 2;   // 0..1
    const int warp_n = warp & 3;    // 0..3
    const int m0 = blockIdx.x * 128;
    const int v0 = blockIdx.y * 128;

    const uint32_t sA = (uint32_t)__cvta_generic_to_shared(smem);
    const uint32_t sB = sA + 32768;   // A: 2 x 16KB, B: 2 x 16KB

    float acc[4][4][4];
    #pragma unroll
    for (int i = 0; i < 4; i++)
        #pragma unroll
        for (int j = 0; j < 4; j++)
            #pragma unroll
            for (int k = 0; k < 4; k++) acc[i][j][k] = 0.f;

    const int ktiles = H >> 6;
    const int lr = tid >> 3;    // 0..31 (row group)
    const int lc = tid & 7;     // 16B chunk 0..7

    size_t aoff[4], boff[4];
    #pragma unroll
    for (int j = 0; j < 4; j++) {
        aoff[j] = (size_t)(m0 + lr + j * 32) * H;
        int vr = v0 + lr + j * 32;
        if (vr > VDIM - 1) vr = VDIM - 1;   // clamp; clamped rows never stored
        boff[j] = (size_t)vr * H;
    }

    // Prologue: stage 0
    #pragma unroll
    for (int j = 0; j < 4; j++) {
        cp16(sA + swz(lr + j * 32, lc), A + aoff[j] + lc * 8);
        cp16(sB + swz(lr + j * 32, lc), B + boff[j] + lc * 8);
    }
    asm volatile("cp.async.commit_group;\n" ::: "memory");

    for (int kt = 0; kt < ktiles; kt++) {
        if (kt + 1 < ktiles) {
            const int st = (kt + 1) & 1;
            const int kk0 = (kt + 1) * 64;
            #pragma unroll
            for (int j = 0; j < 4; j++) {
                cp16(sA + st * 16384 + swz(lr + j * 32, lc), A + aoff[j] + kk0 + lc * 8);
                cp16(sB + st * 16384 + swz(lr + j * 32, lc), B + boff[j] + kk0 + lc * 8);
            }
        }
        asm volatile("cp.async.commit_group;\n" ::: "memory");
        asm volatile("cp.async.wait_group 1;\n" ::: "memory");
        __syncthreads();

        const int st = kt & 1;
        const uint32_t aBase = sA + st * 16384;
        const uint32_t bBase = sB + st * 16384;

        #pragma unroll
        for (int kk = 0; kk < 4; kk++) {
            uint32_t a[4][4], b[4][2];
            #pragma unroll
            for (int mf = 0; mf < 4; mf++) {
                uint32_t row = warp_m * 64 + mf * 16 + (lane & 15);
                uint32_t chunk = kk * 2 + (lane >> 4);
                asm volatile("ldmatrix.sync.aligned.m8n8.x4.shared.b16 {%0,%1,%2,%3}, [%4];\n"
                    : "=r"(a[mf][0]), "=r"(a[mf][1]), "=r"(a[mf][2]), "=r"(a[mf][3])
                    : "r"(aBase + swz(row, chunk)));
            }
            #pragma unroll
            for (int nf = 0; nf < 4; nf++) {
                uint32_t row = warp_n * 32 + nf * 8 + (lane & 7);
                uint32_t chunk = kk * 2 + ((lane >> 3) & 1);
                asm volatile("ldmatrix.sync.aligned.m8n8.x2.shared.b16 {%0,%1}, [%2];\n"
                    : "=r"(b[nf][0]), "=r"(b[nf][1]) : "r"(bBase + swz(row, chunk)));
            }
            #pragma unroll
            for (int mf = 0; mf < 4; mf++)
                #pragma unroll
                for (int nf = 0; nf < 4; nf++)
                    asm volatile(
                        "mma.sync.aligned.m16n8k16.row.col.f32.bf16.bf16.f32 "
                        "{%0,%1,%2,%3}, {%4,%5,%6,%7}, {%8,%9}, {%0,%1,%2,%3};\n"
                        : "+f"(acc[mf][nf][0]), "+f"(acc[mf][nf][1]),
                          "+f"(acc[mf][nf][2]), "+f"(acc[mf][nf][3])
                        : "r"(a[mf][0]), "r"(a[mf][1]), "r"(a[mf][2]), "r"(a[mf][3]),
                          "r"(b[nf][0]), "r"(b[nf][1]));
        }
        __syncthreads();
    }

    // Epilogue: bf16 stores (reference bf16 quantization grid)
    const int row_in = lane >> 2;
    const int col_in = (lane & 3) * 2;
    #pragma unroll
    for (int mf = 0; mf < 4; mf++) {
        #pragma unroll
        for (int nf = 0; nf < 4; nf++) {
            int n0 = m0 + warp_m * 64 + mf * 16 + row_in;
            int v  = v0 + warp_n * 32 + nf * 8 + col_in;
            __nv_bfloat16* r0 = C + (size_t)n0 * VPAD;
            __nv_bfloat16* r1 = C + (size_t)(n0 + 8) * VPAD;
            if (v + 1 < VDIM) {
                *(__nv_bfloat162*)(r0 + v) = __floats2bfloat162_rn(acc[mf][nf][0], acc[mf][nf][1]);
                *(__nv_bfloat162*)(r1 + v) = __floats2bfloat162_rn(acc[mf][nf][2], acc[mf][nf][3]);
            } else if (v < VDIM) {
                r0[v] = __float2bfloat16_rn(acc[mf][nf][0]);
                r1[v] = __float2bfloat16_rn(acc[mf][nf][2]);
            }
        }
    }
}

// ---------------------------------------------------------------------------
// Fused per-row loss: pass 1 = online lse (both rows); pass 2 (L2-hot) = JSD.
// ---------------------------------------------------------------------------
#define NPAIR (VDIM / 2)   // 25128; tail element VDIM-1 by thread 0
__global__ __launch_bounds__(256) void rowloss_kernel(const int* __restrict__ target) {
    const int n = blockIdx.x;
    const __nv_bfloat16* rs = g_logits_s + (size_t)n * VPAD;
    const __nv_bfloat16* rt = g_logits_t + (size_t)n * VPAD;
    const __nv_bfloat162* rs2 = (const __nv_bfloat162*)rs;
    const __nv_bfloat162* rt2 = (const __nv_bfloat162*)rt;

    __shared__ float sh0[256], sh1[256], sh2[256], sh3[256];
    __shared__ float s_ls, s_lt;

    float ms = -INFINITY, ss = 0.f, mt = -INFINITY, st = 0.f;
    for (int p = threadIdx.x; p < NPAIR; p += 256) {
        __nv_bfloat162 xs2 = rs2[p], xt2 = rt2[p];
        float s0 = __bfloat162float(xs2.x), s1 = __bfloat162float(xs2.y);
        float t0 = __bfloat162float(xt2.x), t1 = __bfloat162float(xt2.y);
        float nms = fmaxf(ms, fmaxf(s0, s1));
        ss = ss * __expf(ms - nms) + __expf(s0 - nms) + __expf(s1 - nms);
        ms = nms;
        float nmt = fmaxf(mt, fmaxf(t0, t1));
        st = st * __expf(mt - nmt) + __expf(t0 - nmt) + __expf(t1 - nmt);
        mt = nmt;
    }
    if (threadIdx.x == 0) {
        float s0 = __bfloat162float(rs[VDIM - 1]);
        float nms = fmaxf(ms, s0);
        ss = ss * __expf(ms - nms) + __expf(s0 - nms); ms = nms;
        float t0 = __bfloat162float(rt[VDIM - 1]);
        float nmt = fmaxf(mt, t0);
        st = st * __expf(mt - nmt) + __expf(t0 - nmt); mt = nmt;
    }
    sh0[threadIdx.x] = ms; sh1[threadIdx.x] = ss;
    sh2[threadIdx.x] = mt; sh3[threadIdx.x] = st;
    __syncthreads();
    for (int off = 128; off > 0; off >>= 1) {
        if (threadIdx.x < off) {
            float m2 = sh0[threadIdx.x + off], s2 = sh1[threadIdx.x + off];
            float m1 = sh0[threadIdx.x],       s1 = sh1[threadIdx.x];
            float nm = fmaxf(m1, m2);
            sh1[threadIdx.x] = s1 * __expf(m1 - nm) + s2 * __expf(m2 - nm);
            sh0[threadIdx.x] = nm;
            m2 = sh2[threadIdx.x + off]; s2 = sh3[threadIdx.x + off];
            m1 = sh2[threadIdx.x];       s1 = sh3[threadIdx.x];
            nm = fmaxf(m1, m2);
            sh3[threadIdx.x] = s1 * __expf(m1 - nm) + s2 * __expf(m2 - nm);
            sh2[threadIdx.x] = nm;
        }
        __syncthreads();
    }
    if (threadIdx.x == 0) {
        s_ls = sh0[0] + __logf(sh1[0]);
        s_lt = sh2[0] + __logf(sh3[0]);
    }
    __syncthreads();
    const float ls = s_ls, lt = s_lt;

    float as = 0.f, at = 0.f;
    for (int p = threadIdx.x; p < NPAIR; p += 256) {
        __nv_bfloat162 s2v = rs2[p], t2v = rt2[p];
        #pragma unroll
        for (int h = 0; h < 2; h++) {
            float sv = __bfloat162float(h ? s2v.y : s2v.x);
            float tv = __bfloat162float(h ? t2v.y : t2v.x);
            float slp = sv - ls, tlp = tv - lt;
            float sp = __expf(slp), tp = __expf(tlp);
            float lm = __logf(0.5f * sp + 0.5f * tp);   // BETA = 0.5
            as += sp * (slp - lm);
            at += tp * (tlp - lm);
        }
    }
    if (threadIdx.x == 0) {
        float slp = __bfloat162float(rs[VDIM - 1]) - ls;
        float tlp = __bfloat162float(rt[VDIM - 1]) - lt;
        float sp = __expf(slp), tp = __expf(tlp);
        float lm = __logf(0.5f * sp + 0.5f * tp);
        as += sp * (slp - lm);
        at += tp * (tlp - lm);
    }
    sh0[threadIdx.x] = as; sh1[threadIdx.x] = at;
    __syncthreads();
    for (int off = 128; off > 0; off >>= 1) {
        if (threadIdx.x < off) {
            sh0[threadIdx.x] += sh0[threadIdx.x + off];
            sh1[threadIdx.x] += sh1[threadIdx.x + off];
        }
        __syncthreads();
    }
    if (threadIdx.x == 0) {
        g_row_kls[n] = sh0[0];
        g_row_klt[n] = sh1[0];
        int tg = target[n];
        bool valid = (tg != -100);
        int tgs = valid ? tg : 0;
        g_row_ce[n]    = valid ? (ls - __bfloat162float(rs[tgs])) : 0.f;
        g_row_valid[n] = valid ? 1.f : 0.f;
    }
}

// ---------------------------------------------------------------------------
// Final combine -> scalar loss (deterministic).
// ---------------------------------------------------------------------------
__global__ __launch_bounds__(256) void combine_kernel(float* __restrict__ out) {
    __shared__ float s0[256], s1[256], s2[256], s3[256];
    float a = 0.f, b = 0.f, c = 0.f, d = 0.f;
    for (int n = threadIdx.x; n < NROWS; n += 256) {
        a += g_row_ce[n];
        b += g_row_valid[n];
        c += g_row_kls[n];
        d += g_row_klt[n];
    }
    s0[threadIdx.x] = a; s1[threadIdx.x] = b; s2[threadIdx.x] = c; s3[threadIdx.x] = d;
    __syncthreads();
    for (int off = 128; off > 0; off >>= 1) {
        if (threadIdx.x < off) {
            s0[threadIdx.x] += s0[threadIdx.x + off];
            s1[threadIdx.x] += s1[threadIdx.x + off];
            s2[threadIdx.x] += s2[threadIdx.x + off];
            s3[threadIdx.x] += s3[threadIdx.x + off];
        }
        __syncthreads();
    }
    if (threadIdx.x == 0) {
        float hard = s0[0] / s1[0];
        float jsd  = (0.5f * s3[0] + 0.5f * s2[0]) / (float)NROWS;  // BETA=0.5
        out[0] = 0.5f * hard + 0.5f * jsd;
    }
}

// ---------------------------------------------------------------------------
// Launch.  Inputs are FLOAT32 (harness widens bf16); identified by size.
// W_t conversion runs on a side stream, overlapped with the student GEMM
// (capture-legal event fork/join).  Stream/events created + destroyed per
// call; creation happens on the host side, outside the graph's nodes.
// ---------------------------------------------------------------------------
extern "C" void kernel_launch(void* const* d_in, const int* in_sizes, int n_in,
                              void* d_out, int out_size) {
    const float* student = nullptr;
    const float* W_s     = nullptr;
    const float* teacher = nullptr;
    const float* W_t     = nullptr;
    const int*   target  = nullptr;

    for (int i = 0; i < n_in; i++) {
        long sz = in_sizes[i];
        if      (sz == (long)NROWS * H_S)      student = (const float*)d_in[i];
        else if (sz == (long)VDIM  * H_S)      W_s     = (const float*)d_in[i];
        else if (sz == (long)NROWS * H_T)      teacher = (const float*)d_in[i];
        else if (sz == (long)VDIM  * H_T)      W_t     = (const float*)d_in[i];
        else if (sz == (long)NROWS)            target  = (const int*)d_in[i];
    }

    __nv_bfloat16 *Cs, *Ct, *Wsb, *Wtb, *asb, *atb;
    cudaGetSymbolAddress((void**)&Cs,  g_logits_s);
    cudaGetSymbolAddress((void**)&Ct,  g_logits_t);
    cudaGetSymbolAddress((void**)&Wsb, g_Ws_bf);
    cudaGetSymbolAddress((void**)&Wtb, g_Wt_bf);
    cudaGetSymbolAddress((void**)&asb, g_as_bf);
    cudaGetSymbolAddress((void**)&atb, g_at_bf);

    cudaFuncSetAttribute(gemm_bf16_kernel,
                         cudaFuncAttributeMaxDynamicSharedMemorySize, 65536);

    cudaStream_t s2;
    cudaStreamCreateWithFlags(&s2, cudaStreamNonBlocking);
    cudaEvent_t e1, e2;
    cudaEventCreateWithFlags(&e1, cudaEventDisableTiming);
    cudaEventCreateWithFlags(&e2, cudaEventDisableTiming);

    // Main stream: activation + W_s conversion
    cvt_kernel<<<1024, 256>>>(student, asb, (size_t)NROWS * H_S / 8);
    cvt_kernel<<<1024, 256>>>(teacher, atb, (size_t)NROWS * H_T / 8);
    cvt_kernel<<<8192, 256>>>(W_s,     Wsb, (size_t)VDIM  * H_S / 8);

    // Fork: W_t conversion on side stream, overlapping the student GEMM
    cudaEventRecord(e1, 0);
    cudaStreamWaitEvent(s2, e1, 0);
    cvt_kernel<<<8192, 256, 0, s2>>>(W_t, Wtb, (size_t)VDIM * H_T / 8);
    cudaEventRecord(e2, s2);

    dim3 ggrid(NROWS / 128, (VDIM + 127) / 128);   // (16, 393), M innermost
    gemm_bf16_kernel<<<ggrid, 256, 65536>>>(asb, Wsb, Cs, H_S);

    // Join: teacher GEMM needs W_t converted
    cudaStreamWaitEvent(0, e2, 0);
    gemm_bf16_kernel<<<ggrid, 256, 65536>>>(atb, Wtb, Ct, H_T);

    rowloss_kernel<<<NROWS, 256>>>(target);
    combine_kernel<<<1, 256>>>((float*)d_out);

    cudaEventDestroy(e1);
    cudaEventDestroy(e2);
    cudaStreamDestroy(s2);
}

// round 12
// speedup vs baseline: 1.5862x; 1.0082x over previous
#include <cuda_runtime.h>
#include <cuda_bf16.h>
#include <cstdint>
#include <math.h>

// Problem constants
#define NROWS 2048
#define VDIM  50257
#define VPAD  50272   // bf16 row stride
#define H_S   2048
#define H_T   4096

// Scratch (static device allocations)
__device__ __nv_bfloat16 g_logits_s[(size_t)NROWS * VPAD];  // 206 MB
__device__ __nv_bfloat16 g_logits_t[(size_t)NROWS * VPAD];  // 206 MB
__device__ __nv_bfloat16 g_Ws_bf[(size_t)VDIM * H_S];       // 206 MB
__device__ __nv_bfloat16 g_Wt_bf[(size_t)VDIM * H_T];       // 412 MB
__device__ __nv_bfloat16 g_as_bf[(size_t)NROWS * H_S];
__device__ __nv_bfloat16 g_at_bf[(size_t)NROWS * H_T];
__device__ float g_lse[2 * NROWS];
__device__ float g_row_ce[NROWS];
__device__ float g_row_valid[NROWS];
__device__ float g_row_kls[NROWS];
__device__ float g_row_klt[NROWS];

// ---------------------------------------------------------------------------
// Helpers
// ---------------------------------------------------------------------------
__device__ __forceinline__ uint32_t swz(uint32_t row, uint32_t chunk) {
    return row * 128u + ((chunk ^ (row & 7u)) << 4);
}
__device__ __forceinline__ void cp16(uint32_t saddr, const void* gaddr) {
    asm volatile("cp.async.cg.shared.global [%0], [%1], 16;\n"
                 :: "r"(saddr), "l"(gaddr) : "memory");
}
__device__ __forceinline__ uint32_t pack_bf16x2(float a, float b) {
    __nv_bfloat162 p = __floats2bfloat162_rn(a, b);
    return *(uint32_t*)&p;
}

// ---------------------------------------------------------------------------
// fp32 -> bf16 (lossless).  8 elems/thread/iter: 2x LDG.128 + 1x STG.128.
// Grid-stride; safe at any grid size (used throttled on the side stream).
// ---------------------------------------------------------------------------
__global__ __launch_bounds__(256) void cvt_kernel(
    const float* __restrict__ src, __nv_bfloat16* __restrict__ dst, size_t n8)
{
    const size_t stride = (size_t)gridDim.x * 256;
    for (size_t i = (size_t)blockIdx.x * 256 + threadIdx.x; i < n8; i += stride) {
        const float4* p = (const float4*)(src + i * 8);
        float4 v0 = p[0], v1 = p[1];
        uint4 o = make_uint4(pack_bf16x2(v0.x, v0.y), pack_bf16x2(v0.z, v0.w),
                             pack_bf16x2(v1.x, v1.y), pack_bf16x2(v1.z, v1.w));
        *(uint4*)(dst + i * 8) = o;
    }
}

// ---------------------------------------------------------------------------
// GEMM (R8 config, frozen): C[n,v] = sum_h A[n,h]*B[v,h]
// bf16 in, fp32 accum, bf16 out.  CTA 128x128x64, 8 warps (2x4), warp 64x32.
// Double-buffered cp.async (wait_group 1), k16 mma + ldmatrix.
// ---------------------------------------------------------------------------
__global__ __launch_bounds__(256) void gemm_bf16_kernel(
    const __nv_bfloat16* __restrict__ A,
    const __nv_bfloat16* __restrict__ B,
    __nv_bfloat16* __restrict__ C,
    int H)
{
    extern __shared__ char smem[];

    const int tid   = threadIdx.x;
    const int lane  = tid & 31;
    const int warp  = tid >> 5;
    const int warp_m = warp >> 2;
    const int warp_n = warp & 3;
    const int m0 = blockIdx.x * 128;
    const int v0 = blockIdx.y * 128;

    const uint32_t sA = (uint32_t)__cvta_generic_to_shared(smem);
    const uint32_t sB = sA + 32768;

    float acc[4][4][4];
    #pragma unroll
    for (int i = 0; i < 4; i++)
        #pragma unroll
        for (int j = 0; j < 4; j++)
            #pragma unroll
            for (int k = 0; k < 4; k++) acc[i][j][k] = 0.f;

    const int ktiles = H >> 6;
    const int lr = tid >> 3;
    const int lc = tid & 7;

    size_t aoff[4], boff[4];
    #pragma unroll
    for (int j = 0; j < 4; j++) {
        aoff[j] = (size_t)(m0 + lr + j * 32) * H;
        int vr = v0 + lr + j * 32;
        if (vr > VDIM - 1) vr = VDIM - 1;
        boff[j] = (size_t)vr * H;
    }

    #pragma unroll
    for (int j = 0; j < 4; j++) {
        cp16(sA + swz(lr + j * 32, lc), A + aoff[j] + lc * 8);
        cp16(sB + swz(lr + j * 32, lc), B + boff[j] + lc * 8);
    }
    asm volatile("cp.async.commit_group;\n" ::: "memory");

    for (int kt = 0; kt < ktiles; kt++) {
        if (kt + 1 < ktiles) {
            const int st = (kt + 1) & 1;
            const int kk0 = (kt + 1) * 64;
            #pragma unroll
            for (int j = 0; j < 4; j++) {
                cp16(sA + st * 16384 + swz(lr + j * 32, lc), A + aoff[j] + kk0 + lc * 8);
                cp16(sB + st * 16384 + swz(lr + j * 32, lc), B + boff[j] + kk0 + lc * 8);
            }
        }
        asm volatile("cp.async.commit_group;\n" ::: "memory");
        asm volatile("cp.async.wait_group 1;\n" ::: "memory");
        __syncthreads();

        const int st = kt & 1;
        const uint32_t aBase = sA + st * 16384;
        const uint32_t bBase = sB + st * 16384;

        #pragma unroll
        for (int kk = 0; kk < 4; kk++) {
            uint32_t a[4][4], b[4][2];
            #pragma unroll
            for (int mf = 0; mf < 4; mf++) {
                uint32_t row = warp_m * 64 + mf * 16 + (lane & 15);
                uint32_t chunk = kk * 2 + (lane >> 4);
                asm volatile("ldmatrix.sync.aligned.m8n8.x4.shared.b16 {%0,%1,%2,%3}, [%4];\n"
                    : "=r"(a[mf][0]), "=r"(a[mf][1]), "=r"(a[mf][2]), "=r"(a[mf][3])
                    : "r"(aBase + swz(row, chunk)));
            }
            #pragma unroll
            for (int nf = 0; nf < 4; nf++) {
                uint32_t row = warp_n * 32 + nf * 8 + (lane & 7);
                uint32_t chunk = kk * 2 + ((lane >> 3) & 1);
                asm volatile("ldmatrix.sync.aligned.m8n8.x2.shared.b16 {%0,%1}, [%2];\n"
                    : "=r"(b[nf][0]), "=r"(b[nf][1]) : "r"(bBase + swz(row, chunk)));
            }
            #pragma unroll
            for (int mf = 0; mf < 4; mf++)
                #pragma unroll
                for (int nf = 0; nf < 4; nf++)
                    asm volatile(
                        "mma.sync.aligned.m16n8k16.row.col.f32.bf16.bf16.f32 "
                        "{%0,%1,%2,%3}, {%4,%5,%6,%7}, {%8,%9}, {%0,%1,%2,%3};\n"
                        : "+f"(acc[mf][nf][0]), "+f"(acc[mf][nf][1]),
                          "+f"(acc[mf][nf][2]), "+f"(acc[mf][nf][3])
                        : "r"(a[mf][0]), "r"(a[mf][1]), "r"(a[mf][2]), "r"(a[mf][3]),
                          "r"(b[nf][0]), "r"(b[nf][1]));
        }
        __syncthreads();
    }

    const int row_in = lane >> 2;
    const int col_in = (lane & 3) * 2;
    #pragma unroll
    for (int mf = 0; mf < 4; mf++) {
        #pragma unroll
        for (int nf = 0; nf < 4; nf++) {
            int n0 = m0 + warp_m * 64 + mf * 16 + row_in;
            int v  = v0 + warp_n * 32 + nf * 8 + col_in;
            __nv_bfloat16* r0 = C + (size_t)n0 * VPAD;
            __nv_bfloat16* r1 = C + (size_t)(n0 + 8) * VPAD;
            if (v + 1 < VDIM) {
                *(__nv_bfloat162*)(r0 + v) = __floats2bfloat162_rn(acc[mf][nf][0], acc[mf][nf][1]);
                *(__nv_bfloat162*)(r1 + v) = __floats2bfloat162_rn(acc[mf][nf][2], acc[mf][nf][3]);
            } else if (v < VDIM) {
                r0[v] = __float2bfloat16_rn(acc[mf][nf][0]);
                r1[v] = __float2bfloat16_rn(acc[mf][nf][2]);
            }
        }
    }
}

// ---------------------------------------------------------------------------
// Per-row logsumexp WITHOUT max-shift (logits bounded; no fp32 overflow).
// Grid-stride over rows -> usable throttled on the side stream.
// ---------------------------------------------------------------------------
#define NPAIR (VDIM / 2)   // 25128; tail element VDIM-1 by thread 0
__global__ __launch_bounds__(256) void lse_kernel(
    const __nv_bfloat16* __restrict__ logits, float* __restrict__ lse_out)
{
    __shared__ float sh[256];
    for (int n = blockIdx.x; n < NROWS; n += gridDim.x) {
        const __nv_bfloat162* row2 =
            (const __nv_bfloat162*)(logits + (size_t)n * VPAD);
        float acc = 0.f;
        for (int p = threadIdx.x; p < NPAIR; p += 256) {
            __nv_bfloat162 x2 = row2[p];
            acc += __expf(__bfloat162float(x2.x)) + __expf(__bfloat162float(x2.y));
        }
        if (threadIdx.x == 0)
            acc += __expf(__bfloat162float(
                logits[(size_t)n * VPAD + VDIM - 1]));
        sh[threadIdx.x] = acc;
        __syncthreads();
        for (int off = 128; off > 0; off >>= 1) {
            if (threadIdx.x < off) sh[threadIdx.x] += sh[threadIdx.x + off];
            __syncthreads();
        }
        if (threadIdx.x == 0) lse_out[n] = __logf(sh[0]);
        __syncthreads();
    }
}

// ---------------------------------------------------------------------------
// Per-row JSD terms + CE (uses precomputed lse).
// ---------------------------------------------------------------------------
__global__ __launch_bounds__(256) void rowloss_kernel(const int* __restrict__ target) {
    const int n = blockIdx.x;
    const __nv_bfloat16* rs = g_logits_s + (size_t)n * VPAD;
    const __nv_bfloat16* rt = g_logits_t + (size_t)n * VPAD;
    const __nv_bfloat162* rs2 = (const __nv_bfloat162*)rs;
    const __nv_bfloat162* rt2 = (const __nv_bfloat162*)rt;
    const float ls = g_lse[n];
    const float lt = g_lse[NROWS + n];

    float as = 0.f, at = 0.f;
    for (int p = threadIdx.x; p < NPAIR; p += 256) {
        __nv_bfloat162 s2v = rs2[p], t2v = rt2[p];
        #pragma unroll
        for (int h = 0; h < 2; h++) {
            float sv = __bfloat162float(h ? s2v.y : s2v.x);
            float tv = __bfloat162float(h ? t2v.y : t2v.x);
            float slp = sv - ls, tlp = tv - lt;
            float sp = __expf(slp), tp = __expf(tlp);
            float lm = __logf(0.5f * sp + 0.5f * tp);   // BETA = 0.5
            as += sp * (slp - lm);
            at += tp * (tlp - lm);
        }
    }
    if (threadIdx.x == 0) {
        float slp = __bfloat162float(rs[VDIM - 1]) - ls;
        float tlp = __bfloat162float(rt[VDIM - 1]) - lt;
        float sp = __expf(slp), tp = __expf(tlp);
        float lm = __logf(0.5f * sp + 0.5f * tp);
        as += sp * (slp - lm);
        at += tp * (tlp - lm);
    }
    __shared__ float sh0[256], sh1[256];
    sh0[threadIdx.x] = as; sh1[threadIdx.x] = at;
    __syncthreads();
    for (int off = 128; off > 0; off >>= 1) {
        if (threadIdx.x < off) {
            sh0[threadIdx.x] += sh0[threadIdx.x + off];
            sh1[threadIdx.x] += sh1[threadIdx.x + off];
        }
        __syncthreads();
    }
    if (threadIdx.x == 0) {
        g_row_kls[n] = sh0[0];
        g_row_klt[n] = sh1[0];
        int tg = target[n];
        bool valid = (tg != -100);
        int tgs = valid ? tg : 0;
        g_row_ce[n]    = valid ? (ls - __bfloat162float(rs[tgs])) : 0.f;
        g_row_valid[n] = valid ? 1.f : 0.f;
    }
}

// ---------------------------------------------------------------------------
// Final combine -> scalar loss (deterministic).
// ---------------------------------------------------------------------------
__global__ __launch_bounds__(256) void combine_kernel(float* __restrict__ out) {
    __shared__ float s0[256], s1[256], s2[256], s3[256];
    float a = 0.f, b = 0.f, c = 0.f, d = 0.f;
    for (int n = threadIdx.x; n < NROWS; n += 256) {
        a += g_row_ce[n];
        b += g_row_valid[n];
        c += g_row_kls[n];
        d += g_row_klt[n];
    }
    s0[threadIdx.x] = a; s1[threadIdx.x] = b; s2[threadIdx.x] = c; s3[threadIdx.x] = d;
    __syncthreads();
    for (int off = 128; off > 0; off >>= 1) {
        if (threadIdx.x < off) {
            s0[threadIdx.x] += s0[threadIdx.x + off];
            s1[threadIdx.x] += s1[threadIdx.x + off];
            s2[threadIdx.x] += s2[threadIdx.x + off];
            s3[threadIdx.x] += s3[threadIdx.x + off];
        }
        __syncthreads();
    }
    if (threadIdx.x == 0) {
        float hard = s0[0] / s1[0];
        float jsd  = (0.5f * s3[0] + 0.5f * s2[0]) / (float)NROWS;
        out[0] = 0.5f * hard + 0.5f * jsd;
    }
}

// ---------------------------------------------------------------------------
// Launch.  Side-stream kernels use grid=296 (2 CTAs/SM, no smem) so they
// co-reside with the GEMM instead of displacing it.
// ---------------------------------------------------------------------------
extern "C" void kernel_launch(void* const* d_in, const int* in_sizes, int n_in,
                              void* d_out, int out_size) {
    const float* student = nullptr;
    const float* W_s     = nullptr;
    const float* teacher = nullptr;
    const float* W_t     = nullptr;
    const int*   target  = nullptr;

    for (int i = 0; i < n_in; i++) {
        long sz = in_sizes[i];
        if      (sz == (long)NROWS * H_S)      student = (const float*)d_in[i];
        else if (sz == (long)VDIM  * H_S)      W_s     = (const float*)d_in[i];
        else if (sz == (long)NROWS * H_T)      teacher = (const float*)d_in[i];
        else if (sz == (long)VDIM  * H_T)      W_t     = (const float*)d_in[i];
        else if (sz == (long)NROWS)            target  = (const int*)d_in[i];
    }

    __nv_bfloat16 *Cs, *Ct, *Wsb, *Wtb, *asb, *atb;
    float* lse;
    cudaGetSymbolAddress((void**)&Cs,  g_logits_s);
    cudaGetSymbolAddress((void**)&Ct,  g_logits_t);
    cudaGetSymbolAddress((void**)&Wsb, g_Ws_bf);
    cudaGetSymbolAddress((void**)&Wtb, g_Wt_bf);
    cudaGetSymbolAddress((void**)&asb, g_as_bf);
    cudaGetSymbolAddress((void**)&atb, g_at_bf);
    cudaGetSymbolAddress((void**)&lse, g_lse);

    cudaFuncSetAttribute(gemm_bf16_kernel,
                         cudaFuncAttributeMaxDynamicSharedMemorySize, 65536);

    cudaStream_t s2;
    cudaStreamCreateWithFlags(&s2, cudaStreamNonBlocking);
    cudaEvent_t e1, e2, e3, e4;
    cudaEventCreateWithFlags(&e1, cudaEventDisableTiming);
    cudaEventCreateWithFlags(&e2, cudaEventDisableTiming);
    cudaEventCreateWithFlags(&e3, cudaEventDisableTiming);
    cudaEventCreateWithFlags(&e4, cudaEventDisableTiming);

    // Main: student acts + W_s conversion (needed by student GEMM)
    cvt_kernel<<<1024, 256>>>(student, asb, (size_t)NROWS * H_S / 8);
    cvt_kernel<<<8192, 256>>>(W_s,     Wsb, (size_t)VDIM  * H_S / 8);
    cudaEventRecord(e1, 0);

    // Side (throttled): teacher acts + W_t conversion under the student GEMM
    cudaStreamWaitEvent(s2, e1, 0);
    cvt_kernel<<<296, 256, 0, s2>>>(teacher, atb, (size_t)NROWS * H_T / 8);
    cvt_kernel<<<296, 256, 0, s2>>>(W_t,     Wtb, (size_t)VDIM  * H_T / 8);
    cudaEventRecord(e2, s2);

    dim3 ggrid(NROWS / 128, (VDIM + 127) / 128);   // (16, 393), M innermost
    gemm_bf16_kernel<<<ggrid, 256, 65536>>>(asb, Wsb, Cs, H_S);
    cudaEventRecord(e3, 0);

    // Main: teacher GEMM after W_t ready
    cudaStreamWaitEvent(0, e2, 0);
    gemm_bf16_kernel<<<ggrid, 256, 65536>>>(atb, Wtb, Ct, H_T);

    // Side (throttled): student lse under the teacher GEMM
    cudaStreamWaitEvent(s2, e3, 0);
    lse_kernel<<<296, 256, 0, s2>>>(Cs, lse);
    cudaEventRecord(e4, s2);

    // Main: teacher lse, then joint pass 2
    lse_kernel<<<2048, 256>>>(Ct, lse + NROWS);
    cudaStreamWaitEvent(0, e4, 0);
    rowloss_kernel<<<NROWS, 256>>>(target);
    combine_kernel<<<1, 256>>>((float*)d_out);

    cudaEventDestroy(e1);
    cudaEventDestroy(e2);
    cudaEventDestroy(e3);
    cudaEventDestroy(e4);
    cudaStreamDestroy(s2);
}

// round 13
// speedup vs baseline: 1.6079x; 1.0137x over previous
#include <cuda_runtime.h>
#include <cuda_bf16.h>
#include <cstdint>
#include <math.h>

// Problem constants
#define NROWS 2048
#define VDIM  50257
#define VPAD  50272   // bf16 row stride
#define H_S   2048
#define H_T   4096
#define NVT   393     // number of 128-wide v tiles

// Scratch (static device allocations)
__device__ __nv_bfloat16 g_logits_s[(size_t)NROWS * VPAD];  // 206 MB
__device__ __nv_bfloat16 g_logits_t[(size_t)NROWS * VPAD];  // 206 MB
__device__ __nv_bfloat16 g_Ws_bf[(size_t)VDIM * H_S];       // 206 MB
__device__ __nv_bfloat16 g_Wt_bf[(size_t)VDIM * H_T];       // 412 MB
__device__ __nv_bfloat16 g_as_bf[(size_t)NROWS * H_S];
__device__ __nv_bfloat16 g_at_bf[(size_t)NROWS * H_T];
__device__ float g_pse_s[(size_t)NROWS * NVT];  // per-tile sumexp partials
__device__ float g_pse_t[(size_t)NROWS * NVT];
__device__ float g_lse[2 * NROWS];
__device__ float g_row_ce[NROWS];
__device__ float g_row_valid[NROWS];
__device__ float g_row_kls[NROWS];
__device__ float g_row_klt[NROWS];

// ---------------------------------------------------------------------------
// Helpers
// ---------------------------------------------------------------------------
__device__ __forceinline__ uint32_t swz(uint32_t row, uint32_t chunk) {
    return row * 128u + ((chunk ^ (row & 7u)) << 4);
}
__device__ __forceinline__ void cp16(uint32_t saddr, const void* gaddr) {
    asm volatile("cp.async.cg.shared.global [%0], [%1], 16;\n"
                 :: "r"(saddr), "l"(gaddr) : "memory");
}
__device__ __forceinline__ uint32_t pack_bf16x2(float a, float b) {
    __nv_bfloat162 p = __floats2bfloat162_rn(a, b);
    return *(uint32_t*)&p;
}

// ---------------------------------------------------------------------------
// fp32 -> bf16 (lossless).  8 elems/thread/iter.
// ---------------------------------------------------------------------------
__global__ __launch_bounds__(256) void cvt_kernel(
    const float* __restrict__ src, __nv_bfloat16* __restrict__ dst, size_t n8)
{
    const size_t stride = (size_t)gridDim.x * 256;
    for (size_t i = (size_t)blockIdx.x * 256 + threadIdx.x; i < n8; i += stride) {
        const float4* p = (const float4*)(src + i * 8);
        float4 v0 = p[0], v1 = p[1];
        uint4 o = make_uint4(pack_bf16x2(v0.x, v0.y), pack_bf16x2(v0.z, v0.w),
                             pack_bf16x2(v1.x, v1.y), pack_bf16x2(v1.z, v1.w));
        *(uint4*)(dst + i * 8) = o;
    }
}

// ---------------------------------------------------------------------------
// GEMM (R8 core, frozen): C[n,v] = sum_h A[n,h]*B[v,h]
// Additions: (a) optional fused fp32->bf16 conversion side-job (1 LDG.128 /
// thread / k-tile, STG.64 at iteration end) — guaranteed overlap with mma;
// (b) epilogue per-row sumexp partials -> PSE[row][tile_v] (deterministic
// fixed-order smem tree), removing the standalone lse kernels.
// ---------------------------------------------------------------------------
__global__ __launch_bounds__(256, 2) void gemm_bf16_kernel(
    const __nv_bfloat16* __restrict__ A,
    const __nv_bfloat16* __restrict__ B,
    __nv_bfloat16* __restrict__ C,
    float* __restrict__ PSE,
    int H,
    const float* __restrict__ cvt_src,   // may be null
    __nv_bfloat16* __restrict__ cvt_dst,
    size_t cvt_n4)
{
    extern __shared__ char smem[];

    const int tid   = threadIdx.x;
    const int lane  = tid & 31;
    const int warp  = tid >> 5;
    const int warp_m = warp >> 2;
    const int warp_n = warp & 3;
    const int m0 = blockIdx.x * 128;
    const int v0 = blockIdx.y * 128;

    const uint32_t sA = (uint32_t)__cvta_generic_to_shared(smem);
    const uint32_t sB = sA + 32768;

    float acc[4][4][4];
    #pragma unroll
    for (int i = 0; i < 4; i++)
        #pragma unroll
        for (int j = 0; j < 4; j++)
            #pragma unroll
            for (int k = 0; k < 4; k++) acc[i][j][k] = 0.f;

    const int ktiles = H >> 6;
    const int lr = tid >> 3;
    const int lc = tid & 7;
    const size_t flat_cta = (size_t)blockIdx.y * gridDim.x + blockIdx.x;

    size_t aoff[4], boff[4];
    #pragma unroll
    for (int j = 0; j < 4; j++) {
        aoff[j] = (size_t)(m0 + lr + j * 32) * H;
        int vr = v0 + lr + j * 32;
        if (vr > VDIM - 1) vr = VDIM - 1;
        boff[j] = (size_t)vr * H;
    }

    #pragma unroll
    for (int j = 0; j < 4; j++) {
        cp16(sA + swz(lr + j * 32, lc), A + aoff[j] + lc * 8);
        cp16(sB + swz(lr + j * 32, lc), B + boff[j] + lc * 8);
    }
    asm volatile("cp.async.commit_group;\n" ::: "memory");

    for (int kt = 0; kt < ktiles; kt++) {
        // Fused-cvt side job: issue LDG early; STG at iteration end.
        float4 cv;
        bool cvalid = false;
        size_t cq = 0;
        if (cvt_src) {
            cq = (flat_cta * (size_t)ktiles + kt) * 256 + tid;
            if (cq < cvt_n4) { cv = *(const float4*)(cvt_src + cq * 4); cvalid = true; }
        }

        if (kt + 1 < ktiles) {
            const int st = (kt + 1) & 1;
            const int kk0 = (kt + 1) * 64;
            #pragma unroll
            for (int j = 0; j < 4; j++) {
                cp16(sA + st * 16384 + swz(lr + j * 32, lc), A + aoff[j] + kk0 + lc * 8);
                cp16(sB + st * 16384 + swz(lr + j * 32, lc), B + boff[j] + kk0 + lc * 8);
            }
        }
        asm volatile("cp.async.commit_group;\n" ::: "memory");
        asm volatile("cp.async.wait_group 1;\n" ::: "memory");
        __syncthreads();

        const int st = kt & 1;
        const uint32_t aBase = sA + st * 16384;
        const uint32_t bBase = sB + st * 16384;

        #pragma unroll
        for (int kk = 0; kk < 4; kk++) {
            uint32_t a[4][4], b[4][2];
            #pragma unroll
            for (int mf = 0; mf < 4; mf++) {
                uint32_t row = warp_m * 64 + mf * 16 + (lane & 15);
                uint32_t chunk = kk * 2 + (lane >> 4);
                asm volatile("ldmatrix.sync.aligned.m8n8.x4.shared.b16 {%0,%1,%2,%3}, [%4];\n"
                    : "=r"(a[mf][0]), "=r"(a[mf][1]), "=r"(a[mf][2]), "=r"(a[mf][3])
                    : "r"(aBase + swz(row, chunk)));
            }
            #pragma unroll
            for (int nf = 0; nf < 4; nf++) {
                uint32_t row = warp_n * 32 + nf * 8 + (lane & 7);
                uint32_t chunk = kk * 2 + ((lane >> 3) & 1);
                asm volatile("ldmatrix.sync.aligned.m8n8.x2.shared.b16 {%0,%1}, [%2];\n"
                    : "=r"(b[nf][0]), "=r"(b[nf][1]) : "r"(bBase + swz(row, chunk)));
            }
            #pragma unroll
            for (int mf = 0; mf < 4; mf++)
                #pragma unroll
                for (int nf = 0; nf < 4; nf++)
                    asm volatile(
                        "mma.sync.aligned.m16n8k16.row.col.f32.bf16.bf16.f32 "
                        "{%0,%1,%2,%3}, {%4,%5,%6,%7}, {%8,%9}, {%0,%1,%2,%3};\n"
                        : "+f"(acc[mf][nf][0]), "+f"(acc[mf][nf][1]),
                          "+f"(acc[mf][nf][2]), "+f"(acc[mf][nf][3])
                        : "r"(a[mf][0]), "r"(a[mf][1]), "r"(a[mf][2]), "r"(a[mf][3]),
                          "r"(b[nf][0]), "r"(b[nf][1]));
        }

        if (cvalid) {
            *(uint2*)(cvt_dst + cq * 4) =
                make_uint2(pack_bf16x2(cv.x, cv.y), pack_bf16x2(cv.z, cv.w));
        }
        __syncthreads();
    }

    // ---- Epilogue: bf16 stores + per-row sumexp partials ----
    float* part = (float*)smem;   // [128 rows][17] padded, 8.7KB (mainloop done)
    const int row_in = lane >> 2;
    const int col_in = (lane & 3) * 2;
    const int pidx = warp_n * 4 + (lane & 3);

    #pragma unroll
    for (int mf = 0; mf < 4; mf++) {
        float rs0 = 0.f, rs1 = 0.f;
        int rloc = warp_m * 64 + mf * 16 + row_in;
        int n0 = m0 + rloc;
        #pragma unroll
        for (int nf = 0; nf < 4; nf++) {
            int v = v0 + warp_n * 32 + nf * 8 + col_in;
            __nv_bfloat162 p0 = __floats2bfloat162_rn(acc[mf][nf][0], acc[mf][nf][1]);
            __nv_bfloat162 p1 = __floats2bfloat162_rn(acc[mf][nf][2], acc[mf][nf][3]);
            __nv_bfloat16* r0 = C + (size_t)n0 * VPAD;
            __nv_bfloat16* r1 = C + (size_t)(n0 + 8) * VPAD;
            if (v + 1 < VDIM) {
                *(__nv_bfloat162*)(r0 + v) = p0;
                *(__nv_bfloat162*)(r1 + v) = p1;
            } else if (v < VDIM) {
                r0[v] = p0.x;
                r1[v] = p1.x;
            }
            if (v < VDIM) {
                rs0 += __expf(__bfloat162float(p0.x));
                rs1 += __expf(__bfloat162float(p1.x));
            }
            if (v + 1 < VDIM) {
                rs0 += __expf(__bfloat162float(p0.y));
                rs1 += __expf(__bfloat162float(p1.y));
            }
        }
        part[rloc * 17 + pidx]       = rs0;
        part[(rloc + 8) * 17 + pidx] = rs1;
    }
    __syncthreads();
    if (tid < 128) {
        float s = 0.f;
        #pragma unroll
        for (int i = 0; i < 16; i++) s += part[tid * 17 + i];
        PSE[(size_t)(m0 + tid) * NVT + blockIdx.y] = s;
    }
}

// ---------------------------------------------------------------------------
// Deterministic lse from tile partials: one thread per row.
// ---------------------------------------------------------------------------
__global__ __launch_bounds__(256) void lse_reduce_kernel(
    const float* __restrict__ pse, float* __restrict__ lse_out)
{
    int n = blockIdx.x * 256 + threadIdx.x;
    if (n < NROWS) {
        const float* p = pse + (size_t)n * NVT;
        float s = 0.f;
        for (int j = 0; j < NVT; j++) s += p[j];
        lse_out[n] = __logf(s);
    }
}

// ---------------------------------------------------------------------------
// Per-row JSD terms + CE (uses precomputed lse).
// ---------------------------------------------------------------------------
#define NPAIR (VDIM / 2)   // 25128; tail element VDIM-1 by thread 0
__global__ __launch_bounds__(256) void rowloss_kernel(const int* __restrict__ target) {
    const int n = blockIdx.x;
    const __nv_bfloat16* rs = g_logits_s + (size_t)n * VPAD;
    const __nv_bfloat16* rt = g_logits_t + (size_t)n * VPAD;
    const __nv_bfloat162* rs2 = (const __nv_bfloat162*)rs;
    const __nv_bfloat162* rt2 = (const __nv_bfloat162*)rt;
    const float ls = g_lse[n];
    const float lt = g_lse[NROWS + n];

    float as = 0.f, at = 0.f;
    for (int p = threadIdx.x; p < NPAIR; p += 256) {
        __nv_bfloat162 s2v = rs2[p], t2v = rt2[p];
        #pragma unroll
        for (int h = 0; h < 2; h++) {
            float sv = __bfloat162float(h ? s2v.y : s2v.x);
            float tv = __bfloat162float(h ? t2v.y : t2v.x);
            float slp = sv - ls, tlp = tv - lt;
            float sp = __expf(slp), tp = __expf(tlp);
            float lm = __logf(0.5f * sp + 0.5f * tp);   // BETA = 0.5
            as += sp * (slp - lm);
            at += tp * (tlp - lm);
        }
    }
    if (threadIdx.x == 0) {
        float slp = __bfloat162float(rs[VDIM - 1]) - ls;
        float tlp = __bfloat162float(rt[VDIM - 1]) - lt;
        float sp = __expf(slp), tp = __expf(tlp);
        float lm = __logf(0.5f * sp + 0.5f * tp);
        as += sp * (slp - lm);
        at += tp * (tlp - lm);
    }
    __shared__ float sh0[256], sh1[256];
    sh0[threadIdx.x] = as; sh1[threadIdx.x] = at;
    __syncthreads();
    for (int off = 128; off > 0; off >>= 1) {
        if (threadIdx.x < off) {
            sh0[threadIdx.x] += sh0[threadIdx.x + off];
            sh1[threadIdx.x] += sh1[threadIdx.x + off];
        }
        __syncthreads();
    }
    if (threadIdx.x == 0) {
        g_row_kls[n] = sh0[0];
        g_row_klt[n] = sh1[0];
        int tg = target[n];
        bool valid = (tg != -100);
        int tgs = valid ? tg : 0;
        g_row_ce[n]    = valid ? (ls - __bfloat162float(rs[tgs])) : 0.f;
        g_row_valid[n] = valid ? 1.f : 0.f;
    }
}

// ---------------------------------------------------------------------------
// Final combine -> scalar loss (deterministic).
// ---------------------------------------------------------------------------
__global__ __launch_bounds__(256) void combine_kernel(float* __restrict__ out) {
    __shared__ float s0[256], s1[256], s2[256], s3[256];
    float a = 0.f, b = 0.f, c = 0.f, d = 0.f;
    for (int n = threadIdx.x; n < NROWS; n += 256) {
        a += g_row_ce[n];
        b += g_row_valid[n];
        c += g_row_kls[n];
        d += g_row_klt[n];
    }
    s0[threadIdx.x] = a; s1[threadIdx.x] = b; s2[threadIdx.x] = c; s3[threadIdx.x] = d;
    __syncthreads();
    for (int off = 128; off > 0; off >>= 1) {
        if (threadIdx.x < off) {
            s0[threadIdx.x] += s0[threadIdx.x + off];
            s1[threadIdx.x] += s1[threadIdx.x + off];
            s2[threadIdx.x] += s2[threadIdx.x + off];
            s3[threadIdx.x] += s3[threadIdx.x + off];
        }
        __syncthreads();
    }
    if (threadIdx.x == 0) {
        float hard = s0[0] / s1[0];
        float jsd  = (0.5f * s3[0] + 0.5f * s2[0]) / (float)NROWS;  // BETA=0.5
        out[0] = 0.5f * hard + 0.5f * jsd;
    }
}

// ---------------------------------------------------------------------------
// Launch.  Single stream.  W_t conversion is fused into the student GEMM
// (guaranteed in-kernel overlap); lse comes from GEMM epilogue partials.
// ---------------------------------------------------------------------------
extern "C" void kernel_launch(void* const* d_in, const int* in_sizes, int n_in,
                              void* d_out, int out_size) {
    const float* student = nullptr;
    const float* W_s     = nullptr;
    const float* teacher = nullptr;
    const float* W_t     = nullptr;
    const int*   target  = nullptr;

    for (int i = 0; i < n_in; i++) {
        long sz = in_sizes[i];
        if      (sz == (long)NROWS * H_S)      student = (const float*)d_in[i];
        else if (sz == (long)VDIM  * H_S)      W_s     = (const float*)d_in[i];
        else if (sz == (long)NROWS * H_T)      teacher = (const float*)d_in[i];
        else if (sz == (long)VDIM  * H_T)      W_t     = (const float*)d_in[i];
        else if (sz == (long)NROWS)            target  = (const int*)d_in[i];
    }

    __nv_bfloat16 *Cs, *Ct, *Wsb, *Wtb, *asb, *atb;
    float *lse, *pse_s, *pse_t;
    cudaGetSymbolAddress((void**)&Cs,    g_logits_s);
    cudaGetSymbolAddress((void**)&Ct,    g_logits_t);
    cudaGetSymbolAddress((void**)&Wsb,   g_Ws_bf);
    cudaGetSymbolAddress((void**)&Wtb,   g_Wt_bf);
    cudaGetSymbolAddress((void**)&asb,   g_as_bf);
    cudaGetSymbolAddress((void**)&atb,   g_at_bf);
    cudaGetSymbolAddress((void**)&lse,   g_lse);
    cudaGetSymbolAddress((void**)&pse_s, g_pse_s);
    cudaGetSymbolAddress((void**)&pse_t, g_pse_t);

    cudaFuncSetAttribute(gemm_bf16_kernel,
                         cudaFuncAttributeMaxDynamicSharedMemorySize, 65536);

    // Serial conversions needed before the student GEMM
    cvt_kernel<<<1024, 256>>>(student, asb, (size_t)NROWS * H_S / 8);
    cvt_kernel<<<1024, 256>>>(teacher, atb, (size_t)NROWS * H_T / 8);
    cvt_kernel<<<8192, 256>>>(W_s,     Wsb, (size_t)VDIM  * H_S / 8);

    dim3 ggrid(NROWS / 128, NVT);   // (16, 393), M innermost for L2 reuse

    // Student GEMM + fused W_t conversion (in-kernel overlap)
    gemm_bf16_kernel<<<ggrid, 256, 65536>>>(
        asb, Wsb, Cs, pse_s, H_S,
        W_t, Wtb, (size_t)VDIM * H_T / 4);

    // Teacher GEMM (W_t now converted; same-stream ordering)
    gemm_bf16_kernel<<<ggrid, 256, 65536>>>(
        atb, Wtb, Ct, pse_t, H_T,
        nullptr, nullptr, 0);

    lse_reduce_kernel<<<8, 256>>>(pse_s, lse);
    lse_reduce_kernel<<<8, 256>>>(pse_t, lse + NROWS);
    rowloss_kernel<<<NROWS, 256>>>(target);
    combine_kernel<<<1, 256>>>((float*)d_out);
}